// round 13
// baseline (speedup 1.0000x reference)
#include <cuda_runtime.h>

#define Bx 32
#define Tt 36
#define Nn 10000
#define Ff 3
#define Hh 10
#define Rr 20
#define NQ (Nn * Ff / 4)   // 7500 float4 per (b,t) row
#define NCHUNK 30          // 30 blocks of 256 threads cover NQ

// Scratch (no device allocation allowed -> __device__ globals).
// Zero-initialized at load; k_final re-zeroes after consuming, so every graph
// replay starts from identical state. No fences needed: the kernel boundary
// orders k_main's atomics before k_final's reads.
__device__ float g_rsum[Bx * Rr];    // per-(b,r) regional sums   (atomic)
__device__ int   g_rcnt[Bx * Rr];    // per-(b,r) regional counts (atomic)
__device__ int   g_nanlist[4096];    // packed b*Nn+n of all-NaN nodes (exp. 0)
__device__ int   g_nancnt;           // list length (reset by k_final)

// ---------------------------------------------------------------------------
// Kernel A (heavy, HBM-bound): grid = (NCHUNK, Bx). R11's kernel with ONE
// change: the divergent f%3 store epilogue (40 scattered STG.32/warp, ~2x
// store sector traffic) is replaced by per-warp smem staging + a warp-
// convergent loop doing contiguous coalesced stores and fully-active
// histogram atomics. __syncwarp only — no block sync, so late warps' loads
// still overlap early warps' stores (the R10 mistake avoided).
//  - 36 coalesced float4 loads per thread (512B per warp-load)
//  - NaN time_means written as-is, patched by k_final (P(all-NaN)=0.05^36~0)
//  - cluster_id int64-vs-int32 detected per block (int64 LE in [0,20) => odd
//    words all zero; false-positive prob for true int32 ~ 20^-64)
// ---------------------------------------------------------------------------
__global__ void k_main(const float4* __restrict__ seq, const int* __restrict__ cl,
                       float* __restrict__ out) {
    __shared__ float s_tm[8][44];    // per-warp staged channel-0 means
    __shared__ float s_rsum[Rr];
    __shared__ int   s_rcnt[Rr];
    __shared__ int   s_flag;

    int tid  = threadIdx.x;
    int lane = tid & 31;
    int wrp  = tid >> 5;
    int b    = blockIdx.y;
    int cx   = blockIdx.x;
    int j    = cx * blockDim.x + tid;   // float4 column in [0, NQ)

    if (tid < Rr) { s_rsum[tid] = 0.f; s_rcnt[tid] = 0; }
    if (tid == 0) s_flag = 1;
    __syncthreads();
    if (tid < 64) {
        bool ok = (cl[2 * tid + 1] == 0) && ((unsigned)cl[2 * tid] < (unsigned)Rr);
        if (!ok) atomicAnd(&s_flag, 0);
    }

    float s0 = 0.f, s1 = 0.f, s2 = 0.f, s3 = 0.f;
    int   c0 = 0,   c1 = 0,   c2 = 0,   c3 = 0;
    if (j < NQ) {
        const float4* p = seq + (size_t)b * Tt * NQ + j;
#pragma unroll 6
        for (int t = 0; t < Tt; t++) {
            float4 v = p[(size_t)t * NQ];
            bool o0 = (v.x == v.x), o1 = (v.y == v.y);
            bool o2 = (v.z == v.z), o3 = (v.w == v.w);
            s0 += o0 ? v.x : 0.f;  c0 += o0;
            s1 += o1 ? v.y : 0.f;  c1 += o1;
            s2 += o2 ? v.z : 0.f;  c2 += o2;
            s3 += o3 ? v.w : 0.f;  c3 += o3;
        }
    }

    // Warp-local node range: this warp covers floats [fbw, fbw+128)
    int fbw  = (cx * 256 + wrp * 32) * 4;
    int n0w  = (fbw + 2) / 3;                 // first node of this warp
    int newd = (fbw + 128 + 2) / 3;           // one past last
    if (newd > Nn) newd = Nn;
    int cntw = newd - n0w;                    // 42 or 43 (0 for idle warps)

    // Stage channel-0 means into this warp's smem slice (divergent, smem-only)
    if (j < NQ) {
        float s[4] = {s0, s1, s2, s3};
        int   c[4] = {c0, c1, c2, c3};
        int f0 = 4 * j;
#pragma unroll
        for (int cc = 0; cc < 4; cc++) {
            int f = f0 + cc;
            if (f % 3 == 0)
                s_tm[wrp][f / 3 - n0w] = s[cc] / (float)c[cc];  // 0/0 -> NaN
        }
    }
    __syncwarp();
    int is64 = s_flag;   // written before the long main loop; safely visible

    // Warp-convergent epilogue: coalesced contiguous stores + active atomics
    float* ob = out + (size_t)b * Hh * Nn;
    for (int i = lane; i < cntw; i += 32) {
        float tm = s_tm[wrp][i];
        int node = n0w + i;
        if (tm == tm) {
            int id = is64 ? cl[2 * node] : cl[node];
            atomicAdd(&s_rsum[id], tm);
            atomicAdd(&s_rcnt[id], 1);
        } else {
            int slot = atomicAdd(&g_nancnt, 1);
            g_nanlist[slot & 4095] = b * Nn + node;
        }
#pragma unroll
        for (int h = 0; h < Hh; h++) ob[(size_t)h * Nn + node] = tm;
    }
    __syncthreads();

    // Fire-and-forget flush (REDG, no return, no fence) and exit
    if (tid < Rr) {
        atomicAdd(&g_rsum[b * Rr + tid], s_rsum[tid]);
        atomicAdd(&g_rcnt[b * Rr + tid], s_rcnt[tid]);
    }
}

// ---------------------------------------------------------------------------
// Kernel B (single block, 640 threads, lean): reads the 1280 accumulator
// words, computes regional[b,r], g1, g2; writes the 6400 regional outputs;
// patches NaN-list entries; resets all scratch for the next graph replay.
// ---------------------------------------------------------------------------
__global__ void k_final(float* __restrict__ out) {
    __shared__ double s_ws[20];
    __shared__ int    s_wc[20];
    __shared__ double s_gs[20];
    __shared__ int    s_gc[20];
    __shared__ float  s_regv[Bx * Rr];
    __shared__ float  s_g1, s_g2;

    int tid  = threadIdx.x;     // 0..639, exactly one (b,r) each
    int lane = tid & 31;
    int wid  = tid >> 5;        // 0..19

    float rs = g_rsum[tid];
    int   rc = g_rcnt[tid];
    float v  = rs / (float)rc;         // 0/0 -> NaN
    s_regv[tid] = v;

    double gs = (double)rs; int gc = rc;
    double ls = (v == v) ? (double)v : 0.0;
    int    lc = (v == v) ? 1 : 0;
#pragma unroll
    for (int o = 16; o; o >>= 1) {
        gs += __shfl_down_sync(0xffffffffu, gs, o);
        gc += __shfl_down_sync(0xffffffffu, gc, o);
        ls += __shfl_down_sync(0xffffffffu, ls, o);
        lc += __shfl_down_sync(0xffffffffu, lc, o);
    }
    if (lane == 0) { s_gs[wid] = gs; s_gc[wid] = gc; s_ws[wid] = ls; s_wc[wid] = lc; }
    __syncthreads();
    if (tid == 0) {
        double tg = 0.0; long long tgc = 0;
        double t2 = 0.0; int t2c = 0;
#pragma unroll
        for (int w = 0; w < 20; w++) {
            tg += s_gs[w]; tgc += s_gc[w];
            t2 += s_ws[w]; t2c += s_wc[w];
        }
        s_g1 = (float)(tg / (double)tgc);
        s_g2 = (float)(t2 / (double)t2c);
    }
    __syncthreads();
    float g1 = s_g1, g2 = s_g2;

    // Regional outputs: [B, H, R]
    float* oreg = out + (size_t)Bx * Hh * Nn;
    for (int i = tid; i < Bx * Hh * Rr; i += blockDim.x) {
        int bb = i / (Hh * Rr);
        int r  = i % Rr;
        float vv = s_regv[bb * Rr + r];
        oreg[i] = (vv == vv) ? vv : g2;
    }

    // Patch all-NaN nodes in out_pred with g1 (expected 0 entries)
    int cnt = g_nancnt;
    if (cnt > 4096) cnt = 4096;
    for (int i = tid; i < cnt; i += blockDim.x) {
        int packed = g_nanlist[i];
        int bb = packed / Nn;
        int n  = packed - bb * Nn;
        float* o = out + (size_t)bb * Hh * Nn + n;
#pragma unroll
        for (int h = 0; h < Hh; h++) o[(size_t)h * Nn] = g1;
    }
    __syncthreads();

    // Reset scratch for the next graph replay
    g_rsum[tid] = 0.f;
    g_rcnt[tid] = 0;
    if (tid == 0) g_nancnt = 0;
}

extern "C" void kernel_launch(void* const* d_in, const int* in_sizes, int n_in,
                              void* d_out, int out_size) {
    (void)in_sizes; (void)n_in; (void)out_size;
    const float4* seq = (const float4*)d_in[0];
    const int*    cl  = (const int*)d_in[1];
    float*        out = (float*)d_out;

    k_main<<<dim3(NCHUNK, Bx), 256>>>(seq, cl, out);
    k_final<<<1, Bx * Rr>>>(out);
}

// round 14
// speedup vs baseline: 1.2631x; 1.2631x over previous
#include <cuda_runtime.h>

#define Bx 32
#define Tt 36
#define Nn 10000
#define Ff 3
#define Hh 10
#define Rr 20
#define NQ (Nn * Ff / 4)   // 7500 float4 per (b,t) row
#define NCHUNK 30          // 30 blocks of 256 threads cover NQ

// Scratch (no device allocation allowed -> __device__ globals).
// Zero-initialized at load; k_final re-zeroes after consuming, so every graph
// replay starts from identical state. No fences needed: the kernel boundary
// orders k_main's atomics before k_final's reads.
__device__ float g_rsum[Bx * Rr];    // per-(b,r) regional sums   (atomic)
__device__ int   g_rcnt[Bx * Rr];    // per-(b,r) regional counts (atomic)
__device__ int   g_nanlist[4096];    // packed b*Nn+n of all-NaN nodes (exp. 0)
__device__ int   g_nancnt;           // list length (reset by k_final)

// ---------------------------------------------------------------------------
// Kernel A (heavy, HBM-bound): grid = (NCHUNK, Bx). R11's kernel with the
// epilogue's out_pred stores made coalesced via REGISTER SHUFFLES (no smem,
// no syncwarp — the R12 staging overhead is gone):
//  - each thread computes its 4 component means locally (4 FDIV)
//  - convergent 2-iteration loop: lane i owns node n0w+i, pulls the owning
//    lane's mean via 4 shfl + select, stores 32 consecutive floats per
//    warp-store (full 32B sectors vs R11's 50%-utilized 16B-spaced stores)
//  - histogram atomics guarded inside the same convergent loop
//  - 36 coalesced float4 loads per thread (512B per warp-load) unchanged
//  - NaN time_means written as-is, patched by k_final (P(all-NaN)=0.05^36~0)
//  - cluster_id int64-vs-int32 detected per block (int64 LE in [0,20) => odd
//    words all zero; false-positive prob for true int32 ~ 20^-64)
// ---------------------------------------------------------------------------
__global__ void k_main(const float4* __restrict__ seq, const int* __restrict__ cl,
                       float* __restrict__ out) {
    __shared__ float s_rsum[Rr];
    __shared__ int   s_rcnt[Rr];
    __shared__ int   s_flag;

    int tid  = threadIdx.x;
    int lane = tid & 31;
    int wrp  = tid >> 5;
    int b    = blockIdx.y;
    int cx   = blockIdx.x;
    int j    = cx * blockDim.x + tid;   // float4 column in [0, NQ)

    if (tid < Rr) { s_rsum[tid] = 0.f; s_rcnt[tid] = 0; }
    if (tid == 0) s_flag = 1;
    __syncthreads();
    if (tid < 64) {
        bool ok = (cl[2 * tid + 1] == 0) && ((unsigned)cl[2 * tid] < (unsigned)Rr);
        if (!ok) atomicAnd(&s_flag, 0);
    }

    float s0 = 0.f, s1 = 0.f, s2 = 0.f, s3 = 0.f;
    int   c0 = 0,   c1 = 0,   c2 = 0,   c3 = 0;
    if (j < NQ) {
        const float4* p = seq + (size_t)b * Tt * NQ + j;
#pragma unroll 6
        for (int t = 0; t < Tt; t++) {
            float4 v = p[(size_t)t * NQ];
            bool o0 = (v.x == v.x), o1 = (v.y == v.y);
            bool o2 = (v.z == v.z), o3 = (v.w == v.w);
            s0 += o0 ? v.x : 0.f;  c0 += o0;
            s1 += o1 ? v.y : 0.f;  c1 += o1;
            s2 += o2 ? v.z : 0.f;  c2 += o2;
            s3 += o3 ? v.w : 0.f;  c3 += o3;
        }
    }
    // Component means (NaN for c==0 or idle threads; only valid ones consumed)
    float tm0 = s0 / (float)c0, tm1 = s1 / (float)c1;
    float tm2 = s2 / (float)c2, tm3 = s3 / (float)c3;

    __syncthreads();   // s_flag ready
    int is64 = s_flag;

    // Warp-local node range: this warp covers floats [fbw, fbw+128)
    int jbase = cx * 256 + wrp * 32;          // warp's first j
    int fbw   = jbase * 4;
    int n0w   = (fbw + 2) / 3;                // first node of this warp
    int nend  = ((fbw + 128) + 2) / 3;        // one past last
    if (nend > Nn) nend = Nn;
    int cntw  = nend - n0w;                   // <= 43; may be <=0 for idle warps

    // Convergent epilogue: shuffle-gather + coalesced stores + active atomics
    float* ob = out + (size_t)b * Hh * Nn;
#pragma unroll
    for (int it = 0; it < 2; it++) {
        int i = it * 32 + lane;               // warp-slot -> node n0w + i
        int node = n0w + i;
        int f = 3 * node;
        int src = (f >> 2) - jbase;           // owning lane (0..31 when valid)
        int cc  = f & 3;
        unsigned sm = 0xffffffffu;
        float v0 = __shfl_sync(sm, tm0, src & 31);
        float v1 = __shfl_sync(sm, tm1, src & 31);
        float v2 = __shfl_sync(sm, tm2, src & 31);
        float v3 = __shfl_sync(sm, tm3, src & 31);
        float tm = (cc == 0) ? v0 : (cc == 1) ? v1 : (cc == 2) ? v2 : v3;
        if (i < cntw) {
            if (tm == tm) {
                int id = is64 ? cl[2 * node] : cl[node];
                atomicAdd(&s_rsum[id], tm);
                atomicAdd(&s_rcnt[id], 1);
            } else {
                int slot = atomicAdd(&g_nancnt, 1);
                g_nanlist[slot & 4095] = b * Nn + node;
            }
#pragma unroll
            for (int h = 0; h < Hh; h++) ob[(size_t)h * Nn + node] = tm;
        }
    }
    __syncthreads();

    // Fire-and-forget flush (REDG, no return, no fence) and exit
    if (tid < Rr) {
        atomicAdd(&g_rsum[b * Rr + tid], s_rsum[tid]);
        atomicAdd(&g_rcnt[b * Rr + tid], s_rcnt[tid]);
    }
}

// ---------------------------------------------------------------------------
// Kernel B (single block, 640 threads, lean): reads the 1280 accumulator
// words, computes regional[b,r], g1, g2; writes the 6400 regional outputs;
// patches NaN-list entries; resets all scratch for the next graph replay.
// ---------------------------------------------------------------------------
__global__ void k_final(float* __restrict__ out) {
    __shared__ double s_ws[20];
    __shared__ int    s_wc[20];
    __shared__ double s_gs[20];
    __shared__ int    s_gc[20];
    __shared__ float  s_regv[Bx * Rr];
    __shared__ float  s_g1, s_g2;

    int tid  = threadIdx.x;     // 0..639, exactly one (b,r) each
    int lane = tid & 31;
    int wid  = tid >> 5;        // 0..19

    float rs = g_rsum[tid];
    int   rc = g_rcnt[tid];
    float v  = rs / (float)rc;         // 0/0 -> NaN
    s_regv[tid] = v;

    double gs = (double)rs; int gc = rc;
    double ls = (v == v) ? (double)v : 0.0;
    int    lc = (v == v) ? 1 : 0;
#pragma unroll
    for (int o = 16; o; o >>= 1) {
        gs += __shfl_down_sync(0xffffffffu, gs, o);
        gc += __shfl_down_sync(0xffffffffu, gc, o);
        ls += __shfl_down_sync(0xffffffffu, ls, o);
        lc += __shfl_down_sync(0xffffffffu, lc, o);
    }
    if (lane == 0) { s_gs[wid] = gs; s_gc[wid] = gc; s_ws[wid] = ls; s_wc[wid] = lc; }
    __syncthreads();
    if (tid == 0) {
        double tg = 0.0; long long tgc = 0;
        double t2 = 0.0; int t2c = 0;
#pragma unroll
        for (int w = 0; w < 20; w++) {
            tg += s_gs[w]; tgc += s_gc[w];
            t2 += s_ws[w]; t2c += s_wc[w];
        }
        s_g1 = (float)(tg / (double)tgc);
        s_g2 = (float)(t2 / (double)t2c);
    }
    __syncthreads();
    float g1 = s_g1, g2 = s_g2;

    // Regional outputs: [B, H, R]
    float* oreg = out + (size_t)Bx * Hh * Nn;
    for (int i = tid; i < Bx * Hh * Rr; i += blockDim.x) {
        int bb = i / (Hh * Rr);
        int r  = i % Rr;
        float vv = s_regv[bb * Rr + r];
        oreg[i] = (vv == vv) ? vv : g2;
    }

    // Patch all-NaN nodes in out_pred with g1 (expected 0 entries)
    int cnt = g_nancnt;
    if (cnt > 4096) cnt = 4096;
    for (int i = tid; i < cnt; i += blockDim.x) {
        int packed = g_nanlist[i];
        int bb = packed / Nn;
        int n  = packed - bb * Nn;
        float* o = out + (size_t)bb * Hh * Nn + n;
#pragma unroll
        for (int h = 0; h < Hh; h++) o[(size_t)h * Nn] = g1;
    }
    __syncthreads();

    // Reset scratch for the next graph replay
    g_rsum[tid] = 0.f;
    g_rcnt[tid] = 0;
    if (tid == 0) g_nancnt = 0;
}

extern "C" void kernel_launch(void* const* d_in, const int* in_sizes, int n_in,
                              void* d_out, int out_size) {
    (void)in_sizes; (void)n_in; (void)out_size;
    const float4* seq = (const float4*)d_in[0];
    const int*    cl  = (const int*)d_in[1];
    float*        out = (float*)d_out;

    k_main<<<dim3(NCHUNK, Bx), 256>>>(seq, cl, out);
    k_final<<<1, Bx * Rr>>>(out);
}

// round 15
// speedup vs baseline: 1.2873x; 1.0192x over previous
#include <cuda_runtime.h>

#define Bx 32
#define Tt 36
#define Nn 10000
#define Ff 3
#define Hh 10
#define Rr 20
#define NQ (Nn * Ff / 4)   // 7500 float4 per (b,t) row
#define NCHUNK 30          // 30 blocks of 256 threads cover NQ
#define NBLOCKS (NCHUNK * Bx)

// Scratch (no device allocation allowed -> __device__ globals).
// Zero-initialized at load; the last block resets everything after consuming,
// so every graph replay starts from identical state.
__device__ float g_rsum[Bx * Rr];    // per-(b,r) regional sums   (atomic)
__device__ int   g_rcnt[Bx * Rr];    // per-(b,r) regional counts (atomic)
__device__ int   g_nanlist[4096];    // packed b*Nn+n of all-NaN nodes (exp. 0)
__device__ int   g_nancnt;           // list length
__device__ unsigned g_done;          // finished-block ticket counter

// ---------------------------------------------------------------------------
// Single fused kernel = R14's k_main + fence-free last-block finalization.
//
// Why no __threadfence (the R9 mistake, -20us): the last block only needs the
// accumulator ATOMICS to be visible, not the 14KB of in-flight out_pred
// stores a fence would drain. Ordering used instead:
//   flush via atomicAdd WITH RETURN (ATOMG) -> consume the return value
//   (asm reg dependency) => the atomic has COMPLETED at L2 before the thread
//   proceeds -> __syncthreads -> tid0 takes the ticket. Real-time order
//   guarantees all 40 accumulator updates are globally visible before the
//   ticket increments. Last block reads accumulators with __ldcg (L1 bypass).
//
// Main loop / epilogue identical to R14 (measured ~27us, DRAM-roofline):
//  - 36 coalesced float4 loads per thread (512B per warp-load)
//  - shuffle-gather epilogue: 32-consecutive-float coalesced out_pred stores
//  - NaN time_means written as-is, patched by last block (P=0.05^36 ~ 0)
//  - cluster_id int64-vs-int32 detected per block (int64 LE in [0,20) => odd
//    words all zero; false-positive prob for true int32 ~ 20^-64)
// ---------------------------------------------------------------------------
__global__ void k_main(const float4* __restrict__ seq, const int* __restrict__ cl,
                       float* __restrict__ out) {
    __shared__ float s_rsum[Rr];
    __shared__ int   s_rcnt[Rr];
    __shared__ int   s_flag;
    __shared__ int   s_last;

    int tid  = threadIdx.x;
    int lane = tid & 31;
    int wrp  = tid >> 5;
    int b    = blockIdx.y;
    int cx   = blockIdx.x;
    int j    = cx * blockDim.x + tid;   // float4 column in [0, NQ)

    if (tid < Rr) { s_rsum[tid] = 0.f; s_rcnt[tid] = 0; }
    if (tid == 0) s_flag = 1;
    __syncthreads();
    if (tid < 64) {
        bool ok = (cl[2 * tid + 1] == 0) && ((unsigned)cl[2 * tid] < (unsigned)Rr);
        if (!ok) atomicAnd(&s_flag, 0);
    }

    float s0 = 0.f, s1 = 0.f, s2 = 0.f, s3 = 0.f;
    int   c0 = 0,   c1 = 0,   c2 = 0,   c3 = 0;
    if (j < NQ) {
        const float4* p = seq + (size_t)b * Tt * NQ + j;
#pragma unroll 6
        for (int t = 0; t < Tt; t++) {
            float4 v = p[(size_t)t * NQ];
            bool o0 = (v.x == v.x), o1 = (v.y == v.y);
            bool o2 = (v.z == v.z), o3 = (v.w == v.w);
            s0 += o0 ? v.x : 0.f;  c0 += o0;
            s1 += o1 ? v.y : 0.f;  c1 += o1;
            s2 += o2 ? v.z : 0.f;  c2 += o2;
            s3 += o3 ? v.w : 0.f;  c3 += o3;
        }
    }
    // Component means (NaN for c==0 or idle threads; only valid ones consumed)
    float tm0 = s0 / (float)c0, tm1 = s1 / (float)c1;
    float tm2 = s2 / (float)c2, tm3 = s3 / (float)c3;

    __syncthreads();   // s_flag ready
    int is64 = s_flag;

    // Warp-local node range: this warp covers floats [fbw, fbw+128)
    int jbase = cx * 256 + wrp * 32;          // warp's first j
    int fbw   = jbase * 4;
    int n0w   = (fbw + 2) / 3;                // first node of this warp
    int nend  = ((fbw + 128) + 2) / 3;        // one past last
    if (nend > Nn) nend = Nn;
    int cntw  = nend - n0w;                   // <= 43; may be <=0 for idle warps

    // Convergent epilogue: shuffle-gather + coalesced stores + active atomics
    float* ob = out + (size_t)b * Hh * Nn;
#pragma unroll
    for (int it = 0; it < 2; it++) {
        int i = it * 32 + lane;               // warp-slot -> node n0w + i
        int node = n0w + i;
        int f = 3 * node;
        int src = (f >> 2) - jbase;           // owning lane (0..31 when valid)
        int cc  = f & 3;
        unsigned sm = 0xffffffffu;
        float v0 = __shfl_sync(sm, tm0, src & 31);
        float v1 = __shfl_sync(sm, tm1, src & 31);
        float v2 = __shfl_sync(sm, tm2, src & 31);
        float v3 = __shfl_sync(sm, tm3, src & 31);
        float tm = (cc == 0) ? v0 : (cc == 1) ? v1 : (cc == 2) ? v2 : v3;
        if (i < cntw) {
            if (tm == tm) {
                int id = is64 ? cl[2 * node] : cl[node];
                atomicAdd(&s_rsum[id], tm);
                atomicAdd(&s_rcnt[id], 1);
            } else {
                // Rare path (expected 0): atomic writes with consumed returns
                // so they are L2-complete before this block's ticket.
                int slot = atomicAdd(&g_nancnt, 1);
                int oldv = atomicExch(&g_nanlist[slot & 4095], b * Nn + node);
                asm volatile("" :: "r"(oldv), "r"(slot));
            }
#pragma unroll
            for (int h = 0; h < Hh; h++) ob[(size_t)h * Nn + node] = tm;
        }
    }
    __syncthreads();

    // Flush with ATOMG (returns consumed => completed at L2 before we pass)
    if (tid < Rr) {
        float ra = atomicAdd(&g_rsum[b * Rr + tid], s_rsum[tid]);
        int   rb = atomicAdd(&g_rcnt[b * Rr + tid], s_rcnt[tid]);
        asm volatile("" :: "f"(ra), "r"(rb));
    }
    __syncthreads();   // whole block past completed flushes

    if (tid == 0) {
        unsigned t = atomicAdd(&g_done, 1u);
        s_last = (t == NBLOCKS - 1);
    }
    __syncthreads();
    if (!s_last) return;

    // ---- last-block finalization (256 threads) -----------------------------
    __shared__ double s_gs[8];
    __shared__ long long s_gc[8];
    __shared__ double s_ws[8];
    __shared__ int    s_wc[8];
    __shared__ float  s_regv[Bx * Rr];
    __shared__ float  s_g1, s_g2;

    double gs = 0.0; long long gc = 0;
    double ls = 0.0; int lc = 0;
    for (int i = tid; i < Bx * Rr; i += 256) {
        float rs = __ldcg(&g_rsum[i]);   // L1 bypass: read L2-coherent state
        int   rc = __ldcg(&g_rcnt[i]);
        float v  = rs / (float)rc;       // 0/0 -> NaN
        s_regv[i] = v;
        gs += (double)rs; gc += rc;
        if (v == v) { ls += (double)v; lc++; }
    }
#pragma unroll
    for (int o = 16; o; o >>= 1) {
        gs += __shfl_down_sync(0xffffffffu, gs, o);
        gc += __shfl_down_sync(0xffffffffu, gc, o);
        ls += __shfl_down_sync(0xffffffffu, ls, o);
        lc += __shfl_down_sync(0xffffffffu, lc, o);
    }
    if (lane == 0) { s_gs[wrp] = gs; s_gc[wrp] = gc; s_ws[wrp] = ls; s_wc[wrp] = lc; }
    __syncthreads();
    if (tid == 0) {
        double tg = 0.0; long long tgc = 0;
        double t2 = 0.0; int t2c = 0;
#pragma unroll
        for (int w = 0; w < 8; w++) {
            tg += s_gs[w]; tgc += s_gc[w];
            t2 += s_ws[w]; t2c += s_wc[w];
        }
        s_g1 = (float)(tg / (double)tgc);
        s_g2 = (float)(t2 / (double)t2c);
    }
    __syncthreads();
    float g1 = s_g1, g2 = s_g2;

    // Regional outputs: [B, H, R]
    float* oreg = out + (size_t)Bx * Hh * Nn;
    for (int i = tid; i < Bx * Hh * Rr; i += 256) {
        int bb = i / (Hh * Rr);
        int r  = i % Rr;
        float vv = s_regv[bb * Rr + r];
        oreg[i] = (vv == vv) ? vv : g2;
    }

    // Patch all-NaN nodes in out_pred with g1 (expected 0 entries)
    int cnt = __ldcg(&g_nancnt);
    if (cnt > 4096) cnt = 4096;
    for (int i = tid; i < cnt; i += 256) {
        int packed = __ldcg(&g_nanlist[i]);
        int bb = packed / Nn;
        int n  = packed - bb * Nn;
        float* o = out + (size_t)bb * Hh * Nn + n;
#pragma unroll
        for (int h = 0; h < Hh; h++) o[(size_t)h * Nn] = g1;
    }
    __syncthreads();

    // Reset all scratch for the next graph replay
    for (int i = tid; i < Bx * Rr; i += 256) { g_rsum[i] = 0.f; g_rcnt[i] = 0; }
    if (tid == 0) { g_nancnt = 0; g_done = 0u; }
}

extern "C" void kernel_launch(void* const* d_in, const int* in_sizes, int n_in,
                              void* d_out, int out_size) {
    (void)in_sizes; (void)n_in; (void)out_size;
    const float4* seq = (const float4*)d_in[0];
    const int*    cl  = (const int*)d_in[1];
    float*        out = (float*)d_out;

    k_main<<<dim3(NCHUNK, Bx), 256>>>(seq, cl, out);
}

// round 16
// speedup vs baseline: 1.4078x; 1.0936x over previous
#include <cuda_runtime.h>

#define Bx 32
#define Tt 36
#define Nn 10000
#define Ff 3
#define Hh 10
#define Rr 20
#define NQ (Nn * Ff / 4)   // 7500 float4 per (b,t) row
#define NCHUNK 30          // 30 blocks of 256 threads cover NQ
#define NBLOCKS (NCHUNK * Bx)

// Scratch (no device allocation allowed -> __device__ globals).
// Zero-initialized at load; the last block resets everything after consuming,
// so every graph replay starts from identical state.
__device__ float g_rsum[Bx * Rr];    // per-(b,r) regional sums   (atomic)
__device__ int   g_rcnt[Bx * Rr];    // per-(b,r) regional counts (atomic)
__device__ int   g_nanlist[4096];    // packed b*Nn+n of all-NaN nodes (exp. 0)
__device__ int   g_nancnt;           // list length
__device__ unsigned g_done;          // finished-block ticket counter

// ---------------------------------------------------------------------------
// Single fused kernel (R15 frame) + ONE change: streaming cache hints.
//   __ldcs on the 138MB input (stream-once; part of the R6 config that hit
//   72% DRAM) and __stcs on the out_pred stores (write-once, never re-read)
//   so the write stream stops write-allocating into L2 against the reads.
//
// Fence-free finalization (R15, proven): flush accumulators via atomicAdd
// WITH RETURN, consume the return (asm reg dependency) => atomic completed at
// L2 before proceeding -> __syncthreads -> tid0 ticket. No MEMBAR, no drain
// of in-flight output stores (the R9 -20us mistake).
//
// Main loop / epilogue otherwise identical to R14/R15:
//  - 36 coalesced float4 loads per thread (512B per warp-load)
//  - shuffle-gather epilogue: 32-consecutive-float coalesced out_pred stores
//  - NaN time_means written as-is, patched by last block (P=0.05^36 ~ 0)
//  - cluster_id int64-vs-int32 detected per block (int64 LE in [0,20) => odd
//    words all zero; false-positive prob for true int32 ~ 20^-64)
// ---------------------------------------------------------------------------
__global__ void k_main(const float4* __restrict__ seq, const int* __restrict__ cl,
                       float* __restrict__ out) {
    __shared__ float s_rsum[Rr];
    __shared__ int   s_rcnt[Rr];
    __shared__ int   s_flag;
    __shared__ int   s_last;

    int tid  = threadIdx.x;
    int lane = tid & 31;
    int wrp  = tid >> 5;
    int b    = blockIdx.y;
    int cx   = blockIdx.x;
    int j    = cx * blockDim.x + tid;   // float4 column in [0, NQ)

    if (tid < Rr) { s_rsum[tid] = 0.f; s_rcnt[tid] = 0; }
    if (tid == 0) s_flag = 1;
    __syncthreads();
    if (tid < 64) {
        bool ok = (cl[2 * tid + 1] == 0) && ((unsigned)cl[2 * tid] < (unsigned)Rr);
        if (!ok) atomicAnd(&s_flag, 0);
    }

    float s0 = 0.f, s1 = 0.f, s2 = 0.f, s3 = 0.f;
    int   c0 = 0,   c1 = 0,   c2 = 0,   c3 = 0;
    if (j < NQ) {
        const float4* p = seq + (size_t)b * Tt * NQ + j;
#pragma unroll 6
        for (int t = 0; t < Tt; t++) {
            float4 v = __ldcs(p + (size_t)t * NQ);
            bool o0 = (v.x == v.x), o1 = (v.y == v.y);
            bool o2 = (v.z == v.z), o3 = (v.w == v.w);
            s0 += o0 ? v.x : 0.f;  c0 += o0;
            s1 += o1 ? v.y : 0.f;  c1 += o1;
            s2 += o2 ? v.z : 0.f;  c2 += o2;
            s3 += o3 ? v.w : 0.f;  c3 += o3;
        }
    }
    // Component means (NaN for c==0 or idle threads; only valid ones consumed)
    float tm0 = s0 / (float)c0, tm1 = s1 / (float)c1;
    float tm2 = s2 / (float)c2, tm3 = s3 / (float)c3;

    __syncthreads();   // s_flag ready
    int is64 = s_flag;

    // Warp-local node range: this warp covers floats [fbw, fbw+128)
    int jbase = cx * 256 + wrp * 32;          // warp's first j
    int fbw   = jbase * 4;
    int n0w   = (fbw + 2) / 3;                // first node of this warp
    int nend  = ((fbw + 128) + 2) / 3;        // one past last
    if (nend > Nn) nend = Nn;
    int cntw  = nend - n0w;                   // <= 43; may be <=0 for idle warps

    // Convergent epilogue: shuffle-gather + coalesced streaming stores
    float* ob = out + (size_t)b * Hh * Nn;
#pragma unroll
    for (int it = 0; it < 2; it++) {
        int i = it * 32 + lane;               // warp-slot -> node n0w + i
        int node = n0w + i;
        int f = 3 * node;
        int src = (f >> 2) - jbase;           // owning lane (0..31 when valid)
        int cc  = f & 3;
        unsigned sm = 0xffffffffu;
        float v0 = __shfl_sync(sm, tm0, src & 31);
        float v1 = __shfl_sync(sm, tm1, src & 31);
        float v2 = __shfl_sync(sm, tm2, src & 31);
        float v3 = __shfl_sync(sm, tm3, src & 31);
        float tm = (cc == 0) ? v0 : (cc == 1) ? v1 : (cc == 2) ? v2 : v3;
        if (i < cntw) {
            if (tm == tm) {
                int id = is64 ? cl[2 * node] : cl[node];
                atomicAdd(&s_rsum[id], tm);
                atomicAdd(&s_rcnt[id], 1);
            } else {
                // Rare path (expected 0): atomic writes with consumed returns
                // so they are L2-complete before this block's ticket.
                int slot = atomicAdd(&g_nancnt, 1);
                int oldv = atomicExch(&g_nanlist[slot & 4095], b * Nn + node);
                asm volatile("" :: "r"(oldv), "r"(slot));
            }
#pragma unroll
            for (int h = 0; h < Hh; h++)
                __stcs(ob + (size_t)h * Nn + node, tm);
        }
    }
    __syncthreads();

    // Flush with ATOMG (returns consumed => completed at L2 before we pass)
    if (tid < Rr) {
        float ra = atomicAdd(&g_rsum[b * Rr + tid], s_rsum[tid]);
        int   rb = atomicAdd(&g_rcnt[b * Rr + tid], s_rcnt[tid]);
        asm volatile("" :: "f"(ra), "r"(rb));
    }
    __syncthreads();   // whole block past completed flushes

    if (tid == 0) {
        unsigned t = atomicAdd(&g_done, 1u);
        s_last = (t == NBLOCKS - 1);
    }
    __syncthreads();
    if (!s_last) return;

    // ---- last-block finalization (256 threads) -----------------------------
    __shared__ double s_gs[8];
    __shared__ long long s_gc[8];
    __shared__ double s_ws[8];
    __shared__ int    s_wc[8];
    __shared__ float  s_regv[Bx * Rr];
    __shared__ float  s_g1, s_g2;

    double gs = 0.0; long long gc = 0;
    double ls = 0.0; int lc = 0;
    for (int i = tid; i < Bx * Rr; i += 256) {
        float rs = __ldcg(&g_rsum[i]);   // L1 bypass: read L2-coherent state
        int   rc = __ldcg(&g_rcnt[i]);
        float v  = rs / (float)rc;       // 0/0 -> NaN
        s_regv[i] = v;
        gs += (double)rs; gc += rc;
        if (v == v) { ls += (double)v; lc++; }
    }
#pragma unroll
    for (int o = 16; o; o >>= 1) {
        gs += __shfl_down_sync(0xffffffffu, gs, o);
        gc += __shfl_down_sync(0xffffffffu, gc, o);
        ls += __shfl_down_sync(0xffffffffu, ls, o);
        lc += __shfl_down_sync(0xffffffffu, lc, o);
    }
    if (lane == 0) { s_gs[wrp] = gs; s_gc[wrp] = gc; s_ws[wrp] = ls; s_wc[wrp] = lc; }
    __syncthreads();
    if (tid == 0) {
        double tg = 0.0; long long tgc = 0;
        double t2 = 0.0; int t2c = 0;
#pragma unroll
        for (int w = 0; w < 8; w++) {
            tg += s_gs[w]; tgc += s_gc[w];
            t2 += s_ws[w]; t2c += s_wc[w];
        }
        s_g1 = (float)(tg / (double)tgc);
        s_g2 = (float)(t2 / (double)t2c);
    }
    __syncthreads();
    float g1 = s_g1, g2 = s_g2;

    // Regional outputs: [B, H, R]
    float* oreg = out + (size_t)Bx * Hh * Nn;
    for (int i = tid; i < Bx * Hh * Rr; i += 256) {
        int bb = i / (Hh * Rr);
        int r  = i % Rr;
        float vv = s_regv[bb * Rr + r];
        oreg[i] = (vv == vv) ? vv : g2;
    }

    // Patch all-NaN nodes in out_pred with g1 (expected 0 entries)
    int cnt = __ldcg(&g_nancnt);
    if (cnt > 4096) cnt = 4096;
    for (int i = tid; i < cnt; i += 256) {
        int packed = __ldcg(&g_nanlist[i]);
        int bb = packed / Nn;
        int n  = packed - bb * Nn;
        float* o = out + (size_t)bb * Hh * Nn + n;
#pragma unroll
        for (int h = 0; h < Hh; h++) o[(size_t)h * Nn] = g1;
    }
    __syncthreads();

    // Reset all scratch for the next graph replay
    for (int i = tid; i < Bx * Rr; i += 256) { g_rsum[i] = 0.f; g_rcnt[i] = 0; }
    if (tid == 0) { g_nancnt = 0; g_done = 0u; }
}

extern "C" void kernel_launch(void* const* d_in, const int* in_sizes, int n_in,
                              void* d_out, int out_size) {
    (void)in_sizes; (void)n_in; (void)out_size;
    const float4* seq = (const float4*)d_in[0];
    const int*    cl  = (const int*)d_in[1];
    float*        out = (float*)d_out;

    k_main<<<dim3(NCHUNK, Bx), 256>>>(seq, cl, out);
}